// round 14
// baseline (speedup 1.0000x reference)
#include <cuda_runtime.h>
#include <math.h>

// ---------------------------------------------------------------------------
// Conv weights in __constant__ memory (R9 win: const/uniform-operand FFMA
// beats the 3-reg rt=2 ceiling; measured fma=55.1% > 50%).
// ---------------------------------------------------------------------------
__constant__ float c_w[13289];

// ---------------------------------------------------------------------------
// Scratch (no allocations allowed -> static __device__ arrays)
// ---------------------------------------------------------------------------
__device__ float g_h1[256 * 3 * 50625];  // [B,3,15,15,15,15]
__device__ float g_h2[256 * 3 * 20736];  // [B,3,12,12,12,12]
__device__ float g_h3[256 * 4 * 6561];   // [B,4,9,9,9,9]
__device__ float g_h4[256 * 5 * 1296];   // [B,5,6,6,6,6]
__device__ float g_h5[256 * 5 * 256];    // [B,5,4,4,4,4] == [B,1280]

// z-row stride: even (8B-aligned pair loads) with odd half (conflict-free
// LDS.64 across oy lanes). 18->18, 15->18, 12->14, 9->10, 6->6.
__host__ __device__ constexpr int rs2_of(int S) {
    int e = (S + 1) & ~1;
    return ((e / 2) & 1) ? e : e + 2;
}

// ---------------------------------------------------------------------------
// 4D conv + bias + relu. Overlap-sliced slab: block covers NS CONTIGUOUS ow
// positions of one batch -> stages K+NS-1 w-slices (shared, not NS*K).
// Thread = (slice, oz-chunk, ox, oy); acc[COUT][OZB] in registers.
// Row values loaded as float2 (LDS.64); weights from __constant__ (uniform).
// KYU: inner-ky unroll factor (K % KYU == 0) to amortize row overhead.
// ---------------------------------------------------------------------------
template <int S, int K, int CIN, int COUT, int WOFF, int NS, int ZSPL,
          int BLK, int MINB, int KYU>
__global__ void __launch_bounds__(BLK, MINB)
conv4d_relu(const float* __restrict__ x,
            const float* __restrict__ bias,
            float* __restrict__ y)
{
    constexpr int T    = S - K + 1;
    constexpr int TT   = T * T;
    constexpr int OZB  = (T + ZSPL - 1) / ZSPL;   // oz per chunk
    constexpr int RS   = rs2_of(S);
    constexpr int S3   = S * S * S;
    constexpr int NW   = K + NS - 1;              // staged w-slices
    constexpr int SLAB = NW * S * S * RS + 8;     // +pad for tail over-read
    constexpr int CK4  = CIN * K * K * K * K;
    constexpr int WIN  = OZB + K - 1;             // row floats needed
    constexpr int NR2  = (WIN + 1) / 2;           // float2 loads per row
    constexpr int GRP  = T / NS;                  // ow groups per batch
    constexpr int PERS = ZSPL * TT;

    static_assert(T % NS == 0, "NS must divide T");
    static_assert(ZSPL == 1 || (OZB % 2) == 0, "oz chunks must start even");
    static_assert(NS * PERS <= BLK, "thread budget too small");
    static_assert(K % KYU == 0, "KYU must divide K");

    extern __shared__ float slab[];               // [SLAB]

    const int tid = threadIdx.x;
    const int b   = blockIdx.x / GRP;
    const int ow0 = (blockIdx.x - b * GRP) * NS;

    const int s   = tid / PERS;
    const int r0  = tid - s * PERS;
    const int zc  = r0 / TT;
    const int rr  = r0 - zc * TT;
    const int ox  = rr / T;
    const int oy  = rr - ox * T;
    const int oz0 = zc * OZB;                     // even by construction
    const bool active = (tid < NS * PERS);

    float acc[COUT][OZB];
#pragma unroll
    for (int co = 0; co < COUT; ++co)
#pragma unroll
        for (int oz = 0; oz < OZB; ++oz) acc[co][oz] = 0.f;

    for (int ci = 0; ci < CIN; ++ci) {
        __syncthreads();   // protect slab from previous iteration's readers
        const float* src = x + ((size_t)(b * CIN + ci) * S + ow0) * S3;
        for (int i = tid; i < NW * S3; i += BLK) {
            int kw = i / S3;
            int r1 = i - kw * S3;
            int xx = r1 / (S * S);
            int r2 = r1 - xx * (S * S);
            int yy = r2 / S;
            int zz = r2 - yy * S;
            slab[((kw * S + xx) * S + yy) * RS + zz] = src[i];
        }
        __syncthreads();

        if (active) {
#pragma unroll 1
            for (int kw = 0; kw < K; ++kw)
#pragma unroll 1
            for (int kx = 0; kx < K; ++kx)
#pragma unroll 1
            for (int ky0 = 0; ky0 < K; ky0 += KYU) {
#pragma unroll
                for (int kyu = 0; kyu < KYU; ++kyu) {
                    const int ky = ky0 + kyu;
                    // slice s uses staged w-slice (s + kw); 8B-aligned base
                    const float* row =
                        &slab[(((s + kw) * S + ox + kx) * S + oy + ky) * RS + oz0];
                    float r[2 * NR2];
#pragma unroll
                    for (int j = 0; j < NR2; ++j) {
                        float2 v = reinterpret_cast<const float2*>(row)[j];
                        r[2 * j]     = v.x;
                        r[2 * j + 1] = v.y;
                    }

                    const int wb = WOFF + ((ci * K + kw) * K + kx) * K * K + ky * K;

#pragma unroll
                    for (int oz = 0; oz < OZB; ++oz)
#pragma unroll
                        for (int co = 0; co < COUT; ++co)
#pragma unroll
                            for (int kz = 0; kz < K; ++kz)
                                acc[co][oz] = fmaf(r[oz + kz],
                                                   c_w[wb + co * CK4 + kz],
                                                   acc[co][oz]);
                }
            }
        }
    }

    if (active) {
        const int ow_t = ow0 + s;
#pragma unroll
        for (int co = 0; co < COUT; ++co) {
            float bv = bias[co];
#pragma unroll
            for (int oz = 0; oz < OZB; ++oz) {
                if (oz0 + oz < T) {
                    float v = acc[co][oz] + bv;
                    y[((((((size_t)b * COUT + co) * T + ow_t) * T + ox) * T + oy) * T)
                      + oz0 + oz] = v > 0.f ? v : 0.f;
                }
            }
        }
    }
}

// ---------------------------------------------------------------------------
// Dense head: relu(h @ dw1.T + db1) @ dw2.T + db2 -> softmax over 2 classes.
// ---------------------------------------------------------------------------
__global__ void dense_head(const float* __restrict__ h,
                           const float* __restrict__ dw1,
                           const float* __restrict__ db1,
                           const float* __restrict__ dw2,
                           const float* __restrict__ db2,
                           float* __restrict__ out)
{
    __shared__ float hb[1280];
    __shared__ float a[33];
    const int b   = blockIdx.x;
    const int tid = threadIdx.x;

    for (int i = tid; i < 1280; i += blockDim.x) hb[i] = h[b * 1280 + i];
    __syncthreads();

    const int warp = tid >> 5, lane = tid & 31;
    const int nwarps = blockDim.x >> 5;
    for (int co = warp; co < 33; co += nwarps) {
        float s = 0.f;
        for (int i = lane; i < 1280; i += 32) s += hb[i] * dw1[co * 1280 + i];
#pragma unroll
        for (int o = 16; o > 0; o >>= 1) s += __shfl_down_sync(0xffffffffu, s, o);
        if (lane == 0) {
            float v = s + db1[co];
            a[co] = v > 0.f ? v : 0.f;
        }
    }
    __syncthreads();

    if (tid == 0) {
        float z0 = db2[0], z1 = db2[1];
#pragma unroll
        for (int i = 0; i < 33; ++i) {
            z0 += a[i] * dw2[i];
            z1 += a[i] * dw2[33 + i];
        }
        float m  = fmaxf(z0, z1);
        float e0 = expf(z0 - m), e1 = expf(z1 - m);
        float inv = 1.f / (e0 + e1);
        out[2 * b]     = e0 * inv;
        out[2 * b + 1] = e1 * inv;
    }
}

// ---------------------------------------------------------------------------
// Launch
// ---------------------------------------------------------------------------
extern "C" void kernel_launch(void* const* d_in, const int* in_sizes, int n_in,
                              void* d_out, int out_size)
{
    const float* x   = (const float*)d_in[0];
    const float* w1  = (const float*)d_in[1];
    const float* b1  = (const float*)d_in[2];
    const float* w2  = (const float*)d_in[3];
    const float* b2  = (const float*)d_in[4];
    const float* w3  = (const float*)d_in[5];
    const float* b3  = (const float*)d_in[6];
    const float* w4  = (const float*)d_in[7];
    const float* b4  = (const float*)d_in[8];
    const float* w5  = (const float*)d_in[9];
    const float* b5  = (const float*)d_in[10];
    const float* dw1 = (const float*)d_in[11];
    const float* db1 = (const float*)d_in[12];
    const float* dw2 = (const float*)d_in[13];
    const float* db2 = (const float*)d_in[14];
    float* out = (float*)d_out;

    float *h1, *h2, *h3, *h4, *h5;
    cudaGetSymbolAddress((void**)&h1, g_h1);
    cudaGetSymbolAddress((void**)&h2, g_h2);
    cudaGetSymbolAddress((void**)&h3, g_h3);
    cudaGetSymbolAddress((void**)&h4, g_h4);
    cudaGetSymbolAddress((void**)&h5, g_h5);

    // Conv weights -> constant memory (D2D async, graph-capturable).
    cudaMemcpyToSymbolAsync(c_w, w1,  768 * 4,     0 * 4, cudaMemcpyDeviceToDevice, 0);
    cudaMemcpyToSymbolAsync(c_w, w2, 2304 * 4,   768 * 4, cudaMemcpyDeviceToDevice, 0);
    cudaMemcpyToSymbolAsync(c_w, w3, 3072 * 4,  3072 * 4, cudaMemcpyDeviceToDevice, 0);
    cudaMemcpyToSymbolAsync(c_w, w4, 5120 * 4,  6144 * 4, cudaMemcpyDeviceToDevice, 0);
    cudaMemcpyToSymbolAsync(c_w, w5, 2025 * 4, 11264 * 4, cudaMemcpyDeviceToDevice, 0);

    // Configs (T: 15,12,9,6,4):
    // L1: NS=1 ZSPL=2 BLK=480 (450 act) KYU=2  RS=18 smem 93,344B -> 2 blk/SM
    // L2: NS=3 ZSPL=1 BLK=432 (432 act) KYU=1  RS=18 smem 97,232B -> 2 blk/SM
    // L3: NS=3 ZSPL=1 BLK=256 (243 act) KYU=2  RS=14 smem 48,416B -> 4 blk/SM
    // L4: NS=6 ZSPL=1 BLK=224 (216 act) KYU=4  RS=10 smem 29,192B -> grid 256, 1 wave
    // L5: NS=2 ZSPL=2 BLK=64  (64 act)  KYU=3  RS=6  smem  3,488B -> grid 512
    constexpr int sm1 = (4 * 18 * 18 * 18 + 8) * 4;
    constexpr int sm2 = (6 * 15 * 15 * 18 + 8) * 4;
    constexpr int sm3 = (6 * 12 * 12 * 14 + 8) * 4;
    constexpr int sm4 = (9 * 9 * 9 * 10 + 8) * 4;
    constexpr int sm5 = (4 * 6 * 6 * 6 + 8) * 4;

    cudaFuncSetAttribute((conv4d_relu<18, 4, 1, 3, 0, 1, 2, 480, 2, 2>),
                         cudaFuncAttributeMaxDynamicSharedMemorySize, sm1);
    cudaFuncSetAttribute((conv4d_relu<15, 4, 3, 3, 768, 3, 1, 432, 2, 1>),
                         cudaFuncAttributeMaxDynamicSharedMemorySize, sm2);
    cudaFuncSetAttribute((conv4d_relu<12, 4, 3, 4, 3072, 3, 1, 256, 3, 2>),
                         cudaFuncAttributeMaxDynamicSharedMemorySize, sm3);
    cudaFuncSetAttribute((conv4d_relu<9, 4, 4, 5, 6144, 6, 1, 224, 2, 4>),
                         cudaFuncAttributeMaxDynamicSharedMemorySize, sm4);
    cudaFuncSetAttribute((conv4d_relu<6, 3, 5, 5, 11264, 2, 2, 64, 8, 3>),
                         cudaFuncAttributeMaxDynamicSharedMemorySize, sm5);

    // grids: B * (T / NS)
    conv4d_relu<18, 4, 1, 3, 0, 1, 2, 480, 2, 2>    <<<256 * 15, 480, sm1>>>(x,  b1, h1);
    conv4d_relu<15, 4, 3, 3, 768, 3, 1, 432, 2, 1>  <<<256 * 4,  432, sm2>>>(h1, b2, h2);
    conv4d_relu<12, 4, 3, 4, 3072, 3, 1, 256, 3, 2> <<<256 * 3,  256, sm3>>>(h2, b3, h3);
    conv4d_relu< 9, 4, 4, 5, 6144, 6, 1, 224, 2, 4> <<<256 * 1,  224, sm4>>>(h3, b4, h4);
    conv4d_relu< 6, 3, 5, 5, 11264, 2, 2, 64, 8, 3> <<<256 * 2,   64, sm5>>>(h4, b5, h5);
    dense_head<<<256, 256>>>(h5, dw1, db1, dw2, db2, out);
}

// round 15
// speedup vs baseline: 1.0464x; 1.0464x over previous
#include <cuda_runtime.h>
#include <math.h>

// ---------------------------------------------------------------------------
// Conv weights in __constant__ memory (R9 win, kept ever since).
// ---------------------------------------------------------------------------
__constant__ float c_w[13289];

// ---------------------------------------------------------------------------
// Scratch (no allocations allowed -> static __device__ arrays)
// ---------------------------------------------------------------------------
__device__ float g_h1[256 * 3 * 50625];  // [B,3,15,15,15,15]
__device__ float g_h2[256 * 3 * 20736];  // [B,3,12,12,12,12]
__device__ float g_h3[256 * 4 * 6561];   // [B,4,9,9,9,9]
__device__ float g_h4[256 * 5 * 1296];   // [B,5,6,6,6,6]
__device__ float g_h5[256 * 5 * 256];    // [B,5,4,4,4,4] == [B,1280]

// z-row stride: even (8B-aligned pair loads) with odd half (conflict-free
// LDS.64 across oy lanes). 18->18, 15->18, 12->14, 9->10, 6->6.
__host__ __device__ constexpr int rs2_of(int S) {
    int e = (S + 1) & ~1;
    return ((e / 2) & 1) ? e : e + 2;
}

// ---------------------------------------------------------------------------
// 4D conv + bias + relu. Overlap-sliced slab: block covers NS CONTIGUOUS ow
// positions of one batch -> stages K+NS-1 w-slices (shared, not NS*K).
// Thread = (slice, oz-chunk, ox, oy); acc[COUT][OZB] in registers.
// Row values loaded as float2 (LDS.64); weights from __constant__.
// KYU: inner-ky unroll factor. When RS==S the slab layout equals the source
// layout -> staging becomes a vectorized float4 memcpy.
// ---------------------------------------------------------------------------
template <int S, int K, int CIN, int COUT, int WOFF, int NS, int ZSPL,
          int BLK, int MINB, int KYU>
__global__ void __launch_bounds__(BLK, MINB)
conv4d_relu(const float* __restrict__ x,
            const float* __restrict__ bias,
            float* __restrict__ y)
{
    constexpr int T    = S - K + 1;
    constexpr int TT   = T * T;
    constexpr int OZB  = (T + ZSPL - 1) / ZSPL;   // oz per chunk
    constexpr int RS   = rs2_of(S);
    constexpr int S3   = S * S * S;
    constexpr int NW   = K + NS - 1;              // staged w-slices
    constexpr int SLAB = NW * S * S * RS + 8;     // +pad for tail over-read
    constexpr int CK4  = CIN * K * K * K * K;
    constexpr int WIN  = OZB + K - 1;             // row floats needed
    constexpr int NR2  = (WIN + 1) / 2;           // float2 loads per row
    constexpr int GRP  = T / NS;                  // ow groups per batch
    constexpr int PERS = ZSPL * TT;
    constexpr bool VLOAD = (RS == S) && ((NW * S3) % 4 == 0);

    static_assert(T % NS == 0, "NS must divide T");
    static_assert(ZSPL == 1 || (OZB % 2) == 0, "oz chunks must start even");
    static_assert(NS * PERS <= BLK, "thread budget too small");
    static_assert(K % KYU == 0, "KYU must divide K");

    extern __shared__ float slab[];               // [SLAB]

    const int tid = threadIdx.x;
    const int b   = blockIdx.x / GRP;
    const int ow0 = (blockIdx.x - b * GRP) * NS;

    const int s   = tid / PERS;
    const int r0  = tid - s * PERS;
    const int zc  = r0 / TT;
    const int rr  = r0 - zc * TT;
    const int ox  = rr / T;
    const int oy  = rr - ox * T;
    const int oz0 = zc * OZB;                     // even by construction
    const bool active = (tid < NS * PERS);

    float acc[COUT][OZB];
#pragma unroll
    for (int co = 0; co < COUT; ++co)
#pragma unroll
        for (int oz = 0; oz < OZB; ++oz) acc[co][oz] = 0.f;

    for (int ci = 0; ci < CIN; ++ci) {
        __syncthreads();   // protect slab from previous iteration's readers
        const float* src = x + ((size_t)(b * CIN + ci) * S + ow0) * S3;
        if (VLOAD) {
            // slab layout == source layout: straight vector copy
            const float4* s4 = reinterpret_cast<const float4*>(src);
            float4*       d4 = reinterpret_cast<float4*>(slab);
            for (int i = tid; i < NW * S3 / 4; i += BLK) d4[i] = s4[i];
        } else {
            for (int i = tid; i < NW * S3; i += BLK) {
                int kw = i / S3;
                int r1 = i - kw * S3;
                int xx = r1 / (S * S);
                int r2 = r1 - xx * (S * S);
                int yy = r2 / S;
                int zz = r2 - yy * S;
                slab[((kw * S + xx) * S + yy) * RS + zz] = src[i];
            }
        }
        __syncthreads();

        if (active) {
#pragma unroll 1
            for (int kw = 0; kw < K; ++kw)
#pragma unroll 1
            for (int kx = 0; kx < K; ++kx)
#pragma unroll 1
            for (int ky0 = 0; ky0 < K; ky0 += KYU) {
#pragma unroll
                for (int kyu = 0; kyu < KYU; ++kyu) {
                    const int ky = ky0 + kyu;
                    // slice s uses staged w-slice (s + kw); 8B-aligned base
                    const float* row =
                        &slab[(((s + kw) * S + ox + kx) * S + oy + ky) * RS + oz0];
                    float r[2 * NR2];
#pragma unroll
                    for (int j = 0; j < NR2; ++j) {
                        float2 v = reinterpret_cast<const float2*>(row)[j];
                        r[2 * j]     = v.x;
                        r[2 * j + 1] = v.y;
                    }

                    const int wb = WOFF + ((ci * K + kw) * K + kx) * K * K + ky * K;

#pragma unroll
                    for (int oz = 0; oz < OZB; ++oz)
#pragma unroll
                        for (int co = 0; co < COUT; ++co)
#pragma unroll
                            for (int kz = 0; kz < K; ++kz)
                                acc[co][oz] = fmaf(r[oz + kz],
                                                   c_w[wb + co * CK4 + kz],
                                                   acc[co][oz]);
                }
            }
        }
    }

    if (active) {
        const int ow_t = ow0 + s;
#pragma unroll
        for (int co = 0; co < COUT; ++co) {
            float bv = bias[co];
#pragma unroll
            for (int oz = 0; oz < OZB; ++oz) {
                if (oz0 + oz < T) {
                    float v = acc[co][oz] + bv;
                    y[((((((size_t)b * COUT + co) * T + ow_t) * T + ox) * T + oy) * T)
                      + oz0 + oz] = v > 0.f ? v : 0.f;
                }
            }
        }
    }
}

// ---------------------------------------------------------------------------
// Dense head: relu(h @ dw1.T + db1) @ dw2.T + db2 -> softmax over 2 classes.
// ---------------------------------------------------------------------------
__global__ void dense_head(const float* __restrict__ h,
                           const float* __restrict__ dw1,
                           const float* __restrict__ db1,
                           const float* __restrict__ dw2,
                           const float* __restrict__ db2,
                           float* __restrict__ out)
{
    __shared__ float hb[1280];
    __shared__ float a[33];
    const int b   = blockIdx.x;
    const int tid = threadIdx.x;

    for (int i = tid; i < 1280; i += blockDim.x) hb[i] = h[b * 1280 + i];
    __syncthreads();

    const int warp = tid >> 5, lane = tid & 31;
    const int nwarps = blockDim.x >> 5;
    for (int co = warp; co < 33; co += nwarps) {
        float s = 0.f;
        for (int i = lane; i < 1280; i += 32) s += hb[i] * dw1[co * 1280 + i];
#pragma unroll
        for (int o = 16; o > 0; o >>= 1) s += __shfl_down_sync(0xffffffffu, s, o);
        if (lane == 0) {
            float v = s + db1[co];
            a[co] = v > 0.f ? v : 0.f;
        }
    }
    __syncthreads();

    if (tid == 0) {
        float z0 = db2[0], z1 = db2[1];
#pragma unroll
        for (int i = 0; i < 33; ++i) {
            z0 += a[i] * dw2[i];
            z1 += a[i] * dw2[33 + i];
        }
        float m  = fmaxf(z0, z1);
        float e0 = expf(z0 - m), e1 = expf(z1 - m);
        float inv = 1.f / (e0 + e1);
        out[2 * b]     = e0 * inv;
        out[2 * b + 1] = e1 * inv;
    }
}

// ---------------------------------------------------------------------------
// Launch
// ---------------------------------------------------------------------------
extern "C" void kernel_launch(void* const* d_in, const int* in_sizes, int n_in,
                              void* d_out, int out_size)
{
    const float* x   = (const float*)d_in[0];
    const float* w1  = (const float*)d_in[1];
    const float* b1  = (const float*)d_in[2];
    const float* w2  = (const float*)d_in[3];
    const float* b2  = (const float*)d_in[4];
    const float* w3  = (const float*)d_in[5];
    const float* b3  = (const float*)d_in[6];
    const float* w4  = (const float*)d_in[7];
    const float* b4  = (const float*)d_in[8];
    const float* w5  = (const float*)d_in[9];
    const float* b5  = (const float*)d_in[10];
    const float* dw1 = (const float*)d_in[11];
    const float* db1 = (const float*)d_in[12];
    const float* dw2 = (const float*)d_in[13];
    const float* db2 = (const float*)d_in[14];
    float* out = (float*)d_out;

    float *h1, *h2, *h3, *h4, *h5;
    cudaGetSymbolAddress((void**)&h1, g_h1);
    cudaGetSymbolAddress((void**)&h2, g_h2);
    cudaGetSymbolAddress((void**)&h3, g_h3);
    cudaGetSymbolAddress((void**)&h4, g_h4);
    cudaGetSymbolAddress((void**)&h5, g_h5);

    // Conv weights -> constant memory (D2D async, graph-capturable).
    cudaMemcpyToSymbolAsync(c_w, w1,  768 * 4,     0 * 4, cudaMemcpyDeviceToDevice, 0);
    cudaMemcpyToSymbolAsync(c_w, w2, 2304 * 4,   768 * 4, cudaMemcpyDeviceToDevice, 0);
    cudaMemcpyToSymbolAsync(c_w, w3, 3072 * 4,  3072 * 4, cudaMemcpyDeviceToDevice, 0);
    cudaMemcpyToSymbolAsync(c_w, w4, 5120 * 4,  6144 * 4, cudaMemcpyDeviceToDevice, 0);
    cudaMemcpyToSymbolAsync(c_w, w5, 2025 * 4, 11264 * 4, cudaMemcpyDeviceToDevice, 0);

    // Configs (T: 15,12,9,6,4) -- R12 bests + R14's L4 + vector loader:
    // L1: NS=1 ZSPL=2 BLK=480 KYU=1  RS=18==S -> VLOAD  smem 93,344B
    // L2: NS=3 ZSPL=1 BLK=432 KYU=1  RS=18             smem 97,232B
    // L3: NS=3 ZSPL=1 BLK=256 KYU=1  RS=14             smem 48,416B
    // L4: NS=6 ZSPL=1 BLK=224 KYU=4  RS=10             smem 29,192B (R14 best)
    // L5: NS=2 ZSPL=2 BLK=64  KYU=1  RS=6==S -> VLOAD  smem  3,488B
    constexpr int sm1 = (4 * 18 * 18 * 18 + 8) * 4;
    constexpr int sm2 = (6 * 15 * 15 * 18 + 8) * 4;
    constexpr int sm3 = (6 * 12 * 12 * 14 + 8) * 4;
    constexpr int sm4 = (9 * 9 * 9 * 10 + 8) * 4;
    constexpr int sm5 = (4 * 6 * 6 * 6 + 8) * 4;

    cudaFuncSetAttribute((conv4d_relu<18, 4, 1, 3, 0, 1, 2, 480, 2, 1>),
                         cudaFuncAttributeMaxDynamicSharedMemorySize, sm1);
    cudaFuncSetAttribute((conv4d_relu<15, 4, 3, 3, 768, 3, 1, 432, 2, 1>),
                         cudaFuncAttributeMaxDynamicSharedMemorySize, sm2);
    cudaFuncSetAttribute((conv4d_relu<12, 4, 3, 4, 3072, 3, 1, 256, 3, 1>),
                         cudaFuncAttributeMaxDynamicSharedMemorySize, sm3);
    cudaFuncSetAttribute((conv4d_relu<9, 4, 4, 5, 6144, 6, 1, 224, 2, 4>),
                         cudaFuncAttributeMaxDynamicSharedMemorySize, sm4);
    cudaFuncSetAttribute((conv4d_relu<6, 3, 5, 5, 11264, 2, 2, 64, 8, 1>),
                         cudaFuncAttributeMaxDynamicSharedMemorySize, sm5);

    // grids: B * (T / NS)
    conv4d_relu<18, 4, 1, 3, 0, 1, 2, 480, 2, 1>    <<<256 * 15, 480, sm1>>>(x,  b1, h1);
    conv4d_relu<15, 4, 3, 3, 768, 3, 1, 432, 2, 1>  <<<256 * 4,  432, sm2>>>(h1, b2, h2);
    conv4d_relu<12, 4, 3, 4, 3072, 3, 1, 256, 3, 1> <<<256 * 3,  256, sm3>>>(h2, b3, h3);
    conv4d_relu< 9, 4, 4, 5, 6144, 6, 1, 224, 2, 4> <<<256 * 1,  224, sm4>>>(h3, b4, h4);
    conv4d_relu< 6, 3, 5, 5, 11264, 2, 2, 64, 8, 1> <<<256 * 2,   64, sm5>>>(h4, b5, h5);
    dense_head<<<256, 256>>>(h5, dw1, db1, dw2, db2, out);
}